// round 1
// baseline (speedup 1.0000x reference)
#include <cuda_runtime.h>

#define B_ 4
#define N_ 4096
#define C_ 256
#define M_ (B_ * N_)

#define BM 64
#define BN 64
#define BK 32

// Scratch (device globals: no allocation allowed in kernel_launch)
__device__ float g_W[C_ * C_];        // fused Wv @ Wo, row-major [k][j]
__device__ float g_bias[C_];          // bv @ Wo + bo
__device__ float g_y[M_ * C_];        // pre-LN activations
__device__ float g_sum[B_ * C_];      // per (b,c) sum over N
__device__ float g_sumsq[B_ * C_];    // per (b,c) sum of squares over N
__device__ float g_mean[B_ * C_];
__device__ float g_rstd[B_ * C_];

// ---------------------------------------------------------------------------
// K1: fuse weights/bias, zero the LN accumulators.
// blocks 0..31: 8 rows of W each. block 32: bias + zero stats.
// ---------------------------------------------------------------------------
__global__ __launch_bounds__(256) void k_prep(const float* __restrict__ Wv,
                                              const float* __restrict__ bv,
                                              const float* __restrict__ Wo,
                                              const float* __restrict__ bo) {
    int t = threadIdx.x;
    int bid = blockIdx.x;
    if (bid < 32) {
        __shared__ float s_wv[8][C_];
        int i0 = bid * 8;
        #pragma unroll
        for (int r = 0; r < 8; r++) s_wv[r][t] = Wv[(i0 + r) * C_ + t];
        __syncthreads();
        float acc[8] = {};
        #pragma unroll 4
        for (int k = 0; k < C_; k++) {
            float wo = Wo[k * C_ + t];
            #pragma unroll
            for (int r = 0; r < 8; r++) acc[r] += s_wv[r][k] * wo;
        }
        #pragma unroll
        for (int r = 0; r < 8; r++) g_W[(i0 + r) * C_ + t] = acc[r];
    } else {
        float acc = bo[t];
        for (int k = 0; k < C_; k++) acc += bv[k] * Wo[k * C_ + t];
        g_bias[t] = acc;
        for (int i = t; i < B_ * C_; i += 256) {
            g_sum[i] = 0.f;
            g_sumsq[i] = 0.f;
        }
    }
}

// ---------------------------------------------------------------------------
// K2: y = X @ g_W + g_bias, and accumulate per-(b,c) sum / sumsq.
// Tiles: 64x64 output per block, K chunks of 32. 256 threads, 4x4 microtile.
// ---------------------------------------------------------------------------
__global__ __launch_bounds__(256) void k_gemm(const float* __restrict__ X) {
    __shared__ float As[BK][BM + 4];   // [k][m]
    __shared__ float Bs[BK][BN + 4];   // [k][n]

    int t  = threadIdx.x;
    int tx = t & 15;        // 0..15 -> 4 output cols each
    int ty = t >> 4;        // 0..15 -> 4 output rows each
    int m0 = blockIdx.x * BM;
    int n0 = blockIdx.y * BN;

    float acc[4][4] = {};

    for (int k0 = 0; k0 < C_; k0 += BK) {
        // Load X tile (64 rows x 32 k), transpose into As[k][m]
        #pragma unroll
        for (int i = 0; i < 2; i++) {
            int idx = t + i * 256;          // 0..511 float4 slots
            int row = idx >> 3;             // 0..63
            int kq  = (idx & 7) * 4;        // 0,4,...,28
            float4 v = *(const float4*)&X[(m0 + row) * C_ + k0 + kq];
            As[kq + 0][row] = v.x;
            As[kq + 1][row] = v.y;
            As[kq + 2][row] = v.z;
            As[kq + 3][row] = v.w;
        }
        // Load W tile (32 k x 64 n) into Bs[k][n]
        #pragma unroll
        for (int i = 0; i < 2; i++) {
            int idx = t + i * 256;
            int kr = idx >> 4;              // 0..31
            int nq = (idx & 15) * 4;        // 0,4,...,60
            *(float4*)&Bs[kr][nq] = *(const float4*)&g_W[(k0 + kr) * C_ + n0 + nq];
        }
        __syncthreads();

        #pragma unroll
        for (int k = 0; k < BK; k++) {
            float a[4], b[4];
            *(float4*)a = *(float4*)&As[k][ty * 4];
            *(float4*)b = *(float4*)&Bs[k][tx * 4];
            #pragma unroll
            for (int i = 0; i < 4; i++)
                #pragma unroll
                for (int j = 0; j < 4; j++)
                    acc[i][j] += a[i] * b[j];
        }
        __syncthreads();
    }

    // Epilogue: add bias, write y, accumulate column sums / sumsq
    int bb = m0 >> 12;   // batch (N_=4096 rows per batch; tiles never straddle)
    float bias[4];
    *(float4*)bias = *(const float4*)&g_bias[n0 + tx * 4];

    float cs[4] = {}, cq[4] = {};
    #pragma unroll
    for (int i = 0; i < 4; i++) {
        float4 v;
        v.x = acc[i][0] + bias[0];
        v.y = acc[i][1] + bias[1];
        v.z = acc[i][2] + bias[2];
        v.w = acc[i][3] + bias[3];
        *(float4*)&g_y[(m0 + ty * 4 + i) * C_ + n0 + tx * 4] = v;
        cs[0] += v.x; cs[1] += v.y; cs[2] += v.z; cs[3] += v.w;
        cq[0] += v.x * v.x; cq[1] += v.y * v.y; cq[2] += v.z * v.z; cq[3] += v.w * v.w;
    }

    // Block-level reduce over ty (16 groups), then one atomic per column.
    float* red = &As[0][0];   // 32*68 floats available, need 16*64
    #pragma unroll
    for (int j = 0; j < 4; j++) red[ty * 64 + tx * 4 + j] = cs[j];
    __syncthreads();
    if (ty == 0) {
        #pragma unroll
        for (int j = 0; j < 4; j++) {
            float s = 0.f;
            #pragma unroll
            for (int r = 0; r < 16; r++) s += red[r * 64 + tx * 4 + j];
            atomicAdd(&g_sum[bb * C_ + n0 + tx * 4 + j], s);
        }
    }
    __syncthreads();
    #pragma unroll
    for (int j = 0; j < 4; j++) red[ty * 64 + tx * 4 + j] = cq[j];
    __syncthreads();
    if (ty == 0) {
        #pragma unroll
        for (int j = 0; j < 4; j++) {
            float s = 0.f;
            #pragma unroll
            for (int r = 0; r < 16; r++) s += red[r * 64 + tx * 4 + j];
            atomicAdd(&g_sumsq[bb * C_ + n0 + tx * 4 + j], s);
        }
    }
}

// ---------------------------------------------------------------------------
// K3: finalize LN stats. var = E[y^2] - E[y]^2 (matches reference).
// ---------------------------------------------------------------------------
__global__ void k_stats() {
    int i = blockIdx.x * blockDim.x + threadIdx.x;
    if (i < B_ * C_) {
        float m = g_sum[i] * (1.f / N_);
        float v = g_sumsq[i] * (1.f / N_) - m * m;
        g_mean[i] = m;
        g_rstd[i] = rsqrtf(v + 1e-6f);
    }
}

// ---------------------------------------------------------------------------
// K4: out = relu((y - mean) * rstd * ln_scale + ln_bias) + X
// ---------------------------------------------------------------------------
__global__ __launch_bounds__(256) void k_apply(const float* __restrict__ X,
                                               const float* __restrict__ ls,
                                               const float* __restrict__ lb,
                                               float* __restrict__ out) {
    int idx = blockIdx.x * blockDim.x + threadIdx.x;   // float4 index
    int c4 = idx & (C_ / 4 - 1);                        // 0..63
    int m  = idx >> 6;                                  // row index
    int bb = m >> 12;                                   // batch
    int cb = c4 * 4;

    float4 y = *(const float4*)&g_y[idx * 4];
    float4 x = ((const float4*)X)[idx];
    float4 m4 = *(const float4*)&g_mean[bb * C_ + cb];
    float4 r4 = *(const float4*)&g_rstd[bb * C_ + cb];
    float4 s4 = *(const float4*)&ls[cb];
    float4 b4 = *(const float4*)&lb[cb];

    float4 o;
    o.x = fmaxf((y.x - m4.x) * r4.x * s4.x + b4.x, 0.f) + x.x;
    o.y = fmaxf((y.y - m4.y) * r4.y * s4.y + b4.y, 0.f) + x.y;
    o.z = fmaxf((y.z - m4.z) * r4.z * s4.z + b4.z, 0.f) + x.z;
    o.w = fmaxf((y.w - m4.w) * r4.w * s4.w + b4.w, 0.f) + x.w;
    ((float4*)out)[idx] = o;
}

// ---------------------------------------------------------------------------
extern "C" void kernel_launch(void* const* d_in, const int* in_sizes, int n_in,
                              void* d_out, int out_size) {
    // metadata order: inputs, mask, Wq, bq, Wk, bk, Wv, bv, Wo, bo, ln_scale, ln_bias
    const float* X  = (const float*)d_in[0];
    const float* Wv = (const float*)d_in[6];
    const float* bv = (const float*)d_in[7];
    const float* Wo = (const float*)d_in[8];
    const float* bo = (const float*)d_in[9];
    const float* ls = (const float*)d_in[10];
    const float* lb = (const float*)d_in[11];
    float* out = (float*)d_out;

    k_prep<<<33, 256>>>(Wv, bv, Wo, bo);
    k_gemm<<<dim3(M_ / BM, C_ / BN), 256>>>(X);
    k_stats<<<(B_ * C_ + 255) / 256, 256>>>();
    k_apply<<<(M_ * C_ / 4) / 256, 256>>>(X, ls, lb, out);
}

// round 3
// speedup vs baseline: 1.5539x; 1.5539x over previous
#include <cuda_runtime.h>
#include <cuda_bf16.h>
#include <cstdint>

#define B_ 4
#define N_ 4096
#define C_ 256
#define M_ (B_ * N_)

#define BK 64
#define APAD_ROW 72   // bf16 elements per SMEM row (64 + 8 pad), 144B, 16B-aligned
#define ROWB 144      // bytes per SMEM row

// SMEM byte offsets (dynamic smem)
#define SM_AHI 0
#define SM_ALO (128 * ROWB)                 // 18432
#define SM_BHI (2 * 128 * ROWB)             // 36864
#define SM_BLO (2 * 128 * ROWB + 256 * ROWB) // 73728
#define SM_TOTAL (2 * 128 * ROWB + 2 * 256 * ROWB) // 110592

// ---------------- device scratch (no allocs allowed) ----------------
__device__ __nv_bfloat16 g_Bhi[C_ * C_];   // W^T hi, [n][k]
__device__ __nv_bfloat16 g_Blo[C_ * C_];   // W^T lo, [n][k]
__device__ float g_y[M_ * C_];             // pre-LN activations
__device__ float g_sum[B_ * C_];
__device__ float g_sumsq[B_ * C_];
__device__ float g_mean[B_ * C_];
__device__ float g_rstd[B_ * C_];

__device__ __forceinline__ uint32_t smem_u32(const void* p) {
    uint32_t a;
    asm("{ .reg .u64 t; cvta.to.shared.u64 t, %1; cvt.u32.u64 %0, t; }" : "=r"(a) : "l"(p));
    return a;
}
__device__ __forceinline__ void ldmx4(uint32_t* r, uint32_t addr) {
    asm volatile("ldmatrix.sync.aligned.m8n8.x4.shared.b16 {%0,%1,%2,%3}, [%4];"
                 : "=r"(r[0]), "=r"(r[1]), "=r"(r[2]), "=r"(r[3]) : "r"(addr));
}
__device__ __forceinline__ void ldmx2(uint32_t* r, uint32_t addr) {
    asm volatile("ldmatrix.sync.aligned.m8n8.x2.shared.b16 {%0,%1}, [%2];"
                 : "=r"(r[0]), "=r"(r[1]) : "r"(addr));
}
__device__ __forceinline__ void mma16816(float* c, const uint32_t* a, const uint32_t* b) {
    asm volatile(
        "mma.sync.aligned.m16n8k16.row.col.f32.bf16.bf16.f32 "
        "{%0,%1,%2,%3}, {%4,%5,%6,%7}, {%8,%9}, {%0,%1,%2,%3};"
        : "+f"(c[0]), "+f"(c[1]), "+f"(c[2]), "+f"(c[3])
        : "r"(a[0]), "r"(a[1]), "r"(a[2]), "r"(a[3]), "r"(b[0]), "r"(b[1]));
}

// ---------------------------------------------------------------------------
// K1: fuse W = Wv@Wo in fp32, emit transposed bf16 hi/lo. Zero stat accums.
// (bias provably cancels through the N-axis LayerNorm -> dropped.)
// ---------------------------------------------------------------------------
__global__ __launch_bounds__(256) void k_prep(const float* __restrict__ Wv,
                                              const float* __restrict__ Wo) {
    int t = threadIdx.x;
    int bid = blockIdx.x;
    if (bid < 32) {
        __shared__ float s_wv[8][C_];
        int i0 = bid * 8;
        #pragma unroll
        for (int r = 0; r < 8; r++) s_wv[r][t] = Wv[(i0 + r) * C_ + t];
        __syncthreads();
        float acc[8] = {};
        #pragma unroll 4
        for (int k = 0; k < C_; k++) {
            float wo = Wo[k * C_ + t];
            #pragma unroll
            for (int r = 0; r < 8; r++) acc[r] += s_wv[r][k] * wo;
        }
        // B operand is W^T: [n=t][k=i0+r]
        #pragma unroll
        for (int r = 0; r < 8; r++) {
            float w = acc[r];
            __nv_bfloat16 h = __float2bfloat16(w);
            g_Bhi[t * C_ + i0 + r] = h;
            g_Blo[t * C_ + i0 + r] = __float2bfloat16(w - __bfloat162float(h));
        }
    } else {
        for (int i = t; i < B_ * C_; i += 256) {
            g_sum[i] = 0.f;
            g_sumsq[i] = 0.f;
        }
    }
}

// ---------------------------------------------------------------------------
// K2: y[m0:m0+128, :] = X @ W via mma.sync bf16 split (hi*hi + hi*lo + lo*hi)
// 8 warps: warpM = wid>>2 (2), warpN = wid&3 (4); warp tile 64x64.
// ---------------------------------------------------------------------------
__global__ __launch_bounds__(256, 1) void k_gemm(const float* __restrict__ X) {
    extern __shared__ char smem[];
    uint32_t sb = smem_u32(smem);
    int t = threadIdx.x, wid = t >> 5, lane = t & 31;
    int warpM = wid >> 2, warpN = wid & 3;
    int m0 = blockIdx.x * 128;

    float acc[4][8][4];
    #pragma unroll
    for (int i = 0; i < 4; i++)
        #pragma unroll
        for (int j = 0; j < 8; j++)
            #pragma unroll
            for (int r = 0; r < 4; r++) acc[i][j][r] = 0.f;

    // Per-lane ldmatrix base addresses
    uint32_t aBase = sb + SM_AHI +
        (warpM * 64 + ((lane >> 3) & 1) * 8 + (lane & 7)) * ROWB + (lane >> 4) * 16;
    uint32_t bBase = sb + SM_BHI +
        (warpN * 64 + (lane & 7)) * ROWB + ((lane >> 3) & 1) * 16;

    int q = t & 3, rr = t >> 2;   // loader coords: quarter, row

    for (int c = 0; c < 4; c++) {
        if (c) __syncthreads();
        // ---- load A: 128 rows x 64 k fp32 -> bf16 hi/lo ----
        #pragma unroll
        for (int p = 0; p < 2; p++) {
            int row = p * 64 + rr;
            const float* src = X + (size_t)(m0 + row) * C_ + c * 64 + q * 16;
            float v[16];
            #pragma unroll
            for (int i = 0; i < 4; i++) *(float4*)&v[i * 4] = *(const float4*)(src + i * 4);
            __nv_bfloat16 h[16], l[16];
            #pragma unroll
            for (int i = 0; i < 16; i++) {
                h[i] = __float2bfloat16(v[i]);
                l[i] = __float2bfloat16(v[i] - __bfloat162float(h[i]));
            }
            char* dh = smem + SM_AHI + row * ROWB + q * 32;
            char* dl = smem + SM_ALO + row * ROWB + q * 32;
            *(uint4*)dh = *(uint4*)&h[0]; *(uint4*)(dh + 16) = *(uint4*)&h[8];
            *(uint4*)dl = *(uint4*)&l[0]; *(uint4*)(dl + 16) = *(uint4*)&l[8];
        }
        // ---- load B: 256 rows(n) x 64 k bf16 (presplit) ----
        #pragma unroll
        for (int it = 0; it < 4; it++) {
            int row = it * 64 + rr;
            const __nv_bfloat16* sh = g_Bhi + row * C_ + c * 64 + q * 16;
            const __nv_bfloat16* sl = g_Blo + row * C_ + c * 64 + q * 16;
            char* dh = smem + SM_BHI + row * ROWB + q * 32;
            char* dl = smem + SM_BLO + row * ROWB + q * 32;
            *(uint4*)dh = *(const uint4*)sh; *(uint4*)(dh + 16) = *(const uint4*)(sh + 8);
            *(uint4*)dl = *(const uint4*)sl; *(uint4*)(dl + 16) = *(const uint4*)(sl + 8);
        }
        __syncthreads();

        // ---- MMA: 4 k16-steps ----
        #pragma unroll
        for (int ks = 0; ks < 4; ks++) {
            uint32_t ah[4][4], al[4][4];
            #pragma unroll
            for (int ms = 0; ms < 4; ms++) {
                uint32_t addr = aBase + ms * (16 * ROWB) + ks * 32;
                ldmx4(ah[ms], addr);
                ldmx4(al[ms], addr + (SM_ALO - SM_AHI));
            }
            #pragma unroll
            for (int ns = 0; ns < 8; ns++) {
                uint32_t bh[2], bl[2];
                uint32_t addr = bBase + ns * (8 * ROWB) + ks * 32;
                ldmx2(bh, addr);
                ldmx2(bl, addr + (SM_BLO - SM_BHI));
                #pragma unroll
                for (int ms = 0; ms < 4; ms++) {
                    mma16816(acc[ms][ns], ah[ms], bh);
                    mma16816(acc[ms][ns], ah[ms], bl);
                    mma16816(acc[ms][ns], al[ms], bh);
                }
            }
        }
    }

    // ---- epilogue: write y ----
    int gid = lane >> 2, tig = lane & 3;
    #pragma unroll
    for (int ms = 0; ms < 4; ms++) {
        int row0 = m0 + warpM * 64 + ms * 16 + gid;
        #pragma unroll
        for (int half = 0; half < 2; half++) {
            float* dst = g_y + (size_t)(row0 + half * 8) * C_ + warpN * 64 + tig * 2;
            #pragma unroll
            for (int ns = 0; ns < 8; ns++) {
                float2 v;
                v.x = acc[ms][ns][half * 2 + 0];
                v.y = acc[ms][ns][half * 2 + 1];
                *(float2*)(dst + ns * 8) = v;
            }
        }
    }
}

// ---------------------------------------------------------------------------
// K3: per-(b,c) column sums over N (partial per 128-row slab, atomics).
// ---------------------------------------------------------------------------
__global__ __launch_bounds__(256) void k_colstats() {
    int slab = blockIdx.x;            // 0..127
    int b = slab >> 5;
    int n0 = (slab & 31) * 128;
    int t = threadIdx.x;
    int c4 = t & 63, rg = t >> 6;
    const float* base = g_y + ((size_t)(b * N_ + n0 + rg * 32)) * C_ + c4 * 4;
    float s[4] = {}, qv[4] = {};
    #pragma unroll 8
    for (int i = 0; i < 32; i++) {
        float4 v = *(const float4*)(base + (size_t)i * C_);
        s[0] += v.x; s[1] += v.y; s[2] += v.z; s[3] += v.w;
        qv[0] += v.x * v.x; qv[1] += v.y * v.y; qv[2] += v.z * v.z; qv[3] += v.w * v.w;
    }
    __shared__ float ss[4][C_], qq[4][C_];
    #pragma unroll
    for (int j = 0; j < 4; j++) { ss[rg][c4 * 4 + j] = s[j]; qq[rg][c4 * 4 + j] = qv[j]; }
    __syncthreads();
    if (rg == 0) {
        #pragma unroll
        for (int j = 0; j < 4; j++) {
            int cc = c4 * 4 + j;
            atomicAdd(&g_sum[b * C_ + cc], ss[0][cc] + ss[1][cc] + ss[2][cc] + ss[3][cc]);
            atomicAdd(&g_sumsq[b * C_ + cc], qq[0][cc] + qq[1][cc] + qq[2][cc] + qq[3][cc]);
        }
    }
}

// ---------------------------------------------------------------------------
// K4: finalize LN stats. var = E[y^2] - E[y]^2 (matches reference).
// ---------------------------------------------------------------------------
__global__ void k_stats() {
    int i = blockIdx.x * blockDim.x + threadIdx.x;
    if (i < B_ * C_) {
        float m = g_sum[i] * (1.f / N_);
        float v = g_sumsq[i] * (1.f / N_) - m * m;
        g_mean[i] = m;
        g_rstd[i] = rsqrtf(v + 1e-6f);
    }
}

// ---------------------------------------------------------------------------
// K5: out = relu((y - mean) * rstd * ln_scale + ln_bias) + X
// ---------------------------------------------------------------------------
__global__ __launch_bounds__(256) void k_apply(const float* __restrict__ X,
                                               const float* __restrict__ ls,
                                               const float* __restrict__ lb,
                                               float* __restrict__ out) {
    int idx = blockIdx.x * blockDim.x + threadIdx.x;   // float4 index
    int c4 = idx & (C_ / 4 - 1);
    int m = idx >> 6;
    int bb = m >> 12;
    int cb = c4 * 4;

    float4 y = *(const float4*)&g_y[(size_t)idx * 4];
    float4 x = ((const float4*)X)[idx];
    float4 m4 = *(const float4*)&g_mean[bb * C_ + cb];
    float4 r4 = *(const float4*)&g_rstd[bb * C_ + cb];
    float4 s4 = *(const float4*)&ls[cb];
    float4 b4 = *(const float4*)&lb[cb];

    float4 o;
    o.x = fmaxf((y.x - m4.x) * r4.x * s4.x + b4.x, 0.f) + x.x;
    o.y = fmaxf((y.y - m4.y) * r4.y * s4.y + b4.y, 0.f) + x.y;
    o.z = fmaxf((y.z - m4.z) * r4.z * s4.z + b4.z, 0.f) + x.z;
    o.w = fmaxf((y.w - m4.w) * r4.w * s4.w + b4.w, 0.f) + x.w;
    ((float4*)out)[idx] = o;
}

// ---------------------------------------------------------------------------
extern "C" void kernel_launch(void* const* d_in, const int* in_sizes, int n_in,
                              void* d_out, int out_size) {
    // order: inputs, mask, Wq, bq, Wk, bk, Wv, bv, Wo, bo, ln_scale, ln_bias
    const float* X  = (const float*)d_in[0];
    const float* Wv = (const float*)d_in[6];
    const float* Wo = (const float*)d_in[8];
    const float* ls = (const float*)d_in[10];
    const float* lb = (const float*)d_in[11];
    float* out = (float*)d_out;

    cudaFuncSetAttribute(k_gemm, cudaFuncAttributeMaxDynamicSharedMemorySize,
                         SM_TOTAL);

    k_prep<<<33, 256>>>(Wv, Wo);
    k_gemm<<<M_ / 128, 256, SM_TOTAL>>>(X);
    k_colstats<<<128, 256>>>();
    k_stats<<<(B_ * C_ + 255) / 256, 256>>>();
    k_apply<<<(M_ * C_ / 4) / 256, 256>>>(X, ls, lb, out);
}

// round 4
// speedup vs baseline: 1.6815x; 1.0821x over previous
#include <cuda_runtime.h>
#include <cuda_bf16.h>
#include <cstdint>

#define B_ 4
#define N_ 4096
#define C_ 256
#define M_ (B_ * N_)

#define ROWB 144      // bytes per SMEM row (64 bf16 = 128B + 16B pad)

// SMEM layout (dynamic):
#define SM_AHI 0
#define SM_ALO 18432
#define SM_B0  36864            // buffer 0: hi at +0, lo at +36864
#define BUFSZ  73728
#define SM_TOTAL (36864 + 2 * BUFSZ)   // 184320

// ---------------- device scratch ----------------
__device__ __nv_bfloat16 g_Bhi[C_ * C_];   // W^T hi, [n][k]
__device__ __nv_bfloat16 g_Blo[C_ * C_];   // W^T lo, [n][k]
__device__ float g_y[M_ * C_];             // pre-LN activations
__device__ float g_sum[B_ * C_];
__device__ float g_sumsq[B_ * C_];

__device__ __forceinline__ uint32_t smem_u32(const void* p) {
    uint32_t a;
    asm("{ .reg .u64 t; cvta.to.shared.u64 t, %1; cvt.u32.u64 %0, t; }" : "=r"(a) : "l"(p));
    return a;
}
__device__ __forceinline__ void cp16(uint32_t dst, const void* src) {
    asm volatile("cp.async.cg.shared.global [%0], [%1], 16;" :: "r"(dst), "l"(src));
}
__device__ __forceinline__ void cp_commit() {
    asm volatile("cp.async.commit_group;" ::: "memory");
}
template <int N> __device__ __forceinline__ void cp_wait() {
    asm volatile("cp.async.wait_group %0;" :: "n"(N) : "memory");
}
__device__ __forceinline__ void ldmx4(uint32_t* r, uint32_t addr) {
    asm volatile("ldmatrix.sync.aligned.m8n8.x4.shared.b16 {%0,%1,%2,%3}, [%4];"
                 : "=r"(r[0]), "=r"(r[1]), "=r"(r[2]), "=r"(r[3]) : "r"(addr));
}
__device__ __forceinline__ void ldmx2(uint32_t* r, uint32_t addr) {
    asm volatile("ldmatrix.sync.aligned.m8n8.x2.shared.b16 {%0,%1}, [%2];"
                 : "=r"(r[0]), "=r"(r[1]) : "r"(addr));
}
__device__ __forceinline__ void mma16816(float* c, const uint32_t* a, const uint32_t* b) {
    asm volatile(
        "mma.sync.aligned.m16n8k16.row.col.f32.bf16.bf16.f32 "
        "{%0,%1,%2,%3}, {%4,%5,%6,%7}, {%8,%9}, {%0,%1,%2,%3};"
        : "+f"(c[0]), "+f"(c[1]), "+f"(c[2]), "+f"(c[3])
        : "r"(a[0]), "r"(a[1]), "r"(a[2]), "r"(a[3]), "r"(b[0]), "r"(b[1]));
}

// ---------------------------------------------------------------------------
// K1: fuse W = Wv@Wo in fp32, emit transposed bf16 hi/lo; zero stat accums.
// (Per-channel bias cancels exactly through the N-axis LayerNorm -> dropped.)
// ---------------------------------------------------------------------------
__global__ __launch_bounds__(256) void k_prep(const float* __restrict__ Wv,
                                              const float* __restrict__ Wo) {
    int t = threadIdx.x;
    int bid = blockIdx.x;
    if (bid < 32) {
        __shared__ float s_wv[8][C_];
        int i0 = bid * 8;
        #pragma unroll
        for (int r = 0; r < 8; r++) s_wv[r][t] = Wv[(i0 + r) * C_ + t];
        __syncthreads();
        float acc[8] = {};
        #pragma unroll 4
        for (int k = 0; k < C_; k++) {
            float wo = Wo[k * C_ + t];
            #pragma unroll
            for (int r = 0; r < 8; r++) acc[r] += s_wv[r][k] * wo;
        }
        #pragma unroll
        for (int r = 0; r < 8; r++) {
            float w = acc[r];
            __nv_bfloat16 h = __float2bfloat16(w);
            g_Bhi[t * C_ + i0 + r] = h;
            g_Blo[t * C_ + i0 + r] = __float2bfloat16(w - __bfloat162float(h));
        }
    } else {
        for (int i = t; i < B_ * C_; i += 256) {
            g_sum[i] = 0.f;
            g_sumsq[i] = 0.f;
        }
    }
}

// ---------------------------------------------------------------------------
// K2: y = X @ W (split-bf16 HMMA), pipelined; epilogue fuses column stats.
// ---------------------------------------------------------------------------
__global__ __launch_bounds__(256, 1) void k_gemm(const float* __restrict__ X) {
    extern __shared__ char smem[];
    uint32_t sb = smem_u32(smem);
    int t = threadIdx.x, wid = t >> 5, lane = t & 31;
    int warpM = wid >> 2, warpN = wid & 3;
    int m0 = blockIdx.x * 128;
    int q = t & 3, rr = t >> 2;          // loader coords

    float acc[4][8][4];
    #pragma unroll
    for (int i = 0; i < 4; i++)
        #pragma unroll
        for (int j = 0; j < 8; j++)
            #pragma unroll
            for (int r = 0; r < 4; r++) acc[i][j][r] = 0.f;

    uint32_t aBase = sb + SM_AHI +
        (warpM * 64 + ((lane >> 3) & 1) * 8 + (lane & 7)) * ROWB + (lane >> 4) * 16;

    // ---- B chunk issue via cp.async (16B granules, hi+lo) ----
    auto issueB = [&](int c, int buf) {
        uint32_t bhi = sb + SM_B0 + buf * BUFSZ;
        uint32_t blo = bhi + 36864;
        const char* shi = (const char*)g_Bhi + c * 128 + q * 32;
        const char* slo = (const char*)g_Blo + c * 128 + q * 32;
        #pragma unroll
        for (int it = 0; it < 4; it++) {
            int row = it * 64 + rr;
            uint32_t d = row * ROWB + q * 32;
            const char* sh = shi + (size_t)row * 512;
            const char* sl = slo + (size_t)row * 512;
            cp16(bhi + d, sh);       cp16(bhi + d + 16, sh + 16);
            cp16(blo + d, sl);       cp16(blo + d + 16, sl + 16);
        }
        cp_commit();
    };
    // ---- A chunk prefetch into registers (fp32) ----
    float areg[32];
    auto loadA = [&](int c) {
        #pragma unroll
        for (int p = 0; p < 2; p++) {
            const float* src = X + (size_t)(m0 + p * 64 + rr) * C_ + c * 64 + q * 16;
            #pragma unroll
            for (int i = 0; i < 4; i++)
                *(float4*)&areg[p * 16 + i * 4] = *(const float4*)(src + i * 4);
        }
    };
    // ---- A store: convert fp32 regs -> bf16 hi/lo smem ----
    auto storeA = [&]() {
        #pragma unroll
        for (int p = 0; p < 2; p++) {
            int row = p * 64 + rr;
            __nv_bfloat16 h[16], l[16];
            #pragma unroll
            for (int i = 0; i < 16; i++) {
                float v = areg[p * 16 + i];
                h[i] = __float2bfloat16(v);
                l[i] = __float2bfloat16(v - __bfloat162float(h[i]));
            }
            char* dh = smem + SM_AHI + row * ROWB + q * 32;
            char* dl = smem + SM_ALO + row * ROWB + q * 32;
            *(uint4*)dh = *(uint4*)&h[0]; *(uint4*)(dh + 16) = *(uint4*)&h[8];
            *(uint4*)dl = *(uint4*)&l[0]; *(uint4*)(dl + 16) = *(uint4*)&l[8];
        }
    };

    issueB(0, 0);
    loadA(0);

    for (int c = 0; c < 4; c++) {
        if (c < 3) issueB(c + 1, (c + 1) & 1);
        storeA();
        if (c < 3) cp_wait<1>(); else cp_wait<0>();
        __syncthreads();
        if (c < 3) loadA(c + 1);           // DRAM latency hides under MMAs

        uint32_t bBase = sb + SM_B0 + (c & 1) * BUFSZ +
            (warpN * 64 + (lane & 7)) * ROWB + ((lane >> 3) & 1) * 16;
        #pragma unroll
        for (int ks = 0; ks < 4; ks++) {
            uint32_t ah[4][4], al[4][4];
            #pragma unroll
            for (int ms = 0; ms < 4; ms++) {
                uint32_t addr = aBase + ms * (16 * ROWB) + ks * 32;
                ldmx4(ah[ms], addr);
                ldmx4(al[ms], addr + (SM_ALO - SM_AHI));
            }
            #pragma unroll
            for (int ns = 0; ns < 8; ns++) {
                uint32_t bh[2], bl[2];
                uint32_t addr = bBase + ns * (8 * ROWB) + ks * 32;
                ldmx2(bh, addr);
                ldmx2(bl, addr + 36864);
                #pragma unroll
                for (int ms = 0; ms < 4; ms++) {
                    mma16816(acc[ms][ns], ah[ms], bh);
                    mma16816(acc[ms][ns], ah[ms], bl);
                    mma16816(acc[ms][ns], al[ms], bh);
                }
            }
        }
        __syncthreads();
    }

    // ---- epilogue: write y ----
    int gid = lane >> 2, tig = lane & 3;
    #pragma unroll
    for (int ms = 0; ms < 4; ms++) {
        int row0 = m0 + warpM * 64 + ms * 16 + gid;
        #pragma unroll
        for (int half = 0; half < 2; half++) {
            float* dst = g_y + (size_t)(row0 + half * 8) * C_ + warpN * 64 + tig * 2;
            #pragma unroll
            for (int ns = 0; ns < 8; ns++) {
                float2 v;
                v.x = acc[ms][ns][half * 2 + 0];
                v.y = acc[ms][ns][half * 2 + 1];
                *(float2*)(dst + ns * 8) = v;
            }
        }
    }

    // ---- fused column stats: sum over this warp's 64 rows, then atomics ----
    int b = m0 >> 12;
    #pragma unroll
    for (int ns = 0; ns < 8; ns++) {
        float s0 = 0.f, s1 = 0.f, q0 = 0.f, q1 = 0.f;
        #pragma unroll
        for (int ms = 0; ms < 4; ms++)
            #pragma unroll
            for (int half = 0; half < 2; half++) {
                float v0 = acc[ms][ns][half * 2 + 0];
                float v1 = acc[ms][ns][half * 2 + 1];
                s0 += v0; q0 += v0 * v0;
                s1 += v1; q1 += v1 * v1;
            }
        #pragma unroll
        for (int off = 4; off < 32; off <<= 1) {
            s0 += __shfl_xor_sync(0xFFFFFFFFu, s0, off);
            s1 += __shfl_xor_sync(0xFFFFFFFFu, s1, off);
            q0 += __shfl_xor_sync(0xFFFFFFFFu, q0, off);
            q1 += __shfl_xor_sync(0xFFFFFFFFu, q1, off);
        }
        if (gid == 0) {
            int col = warpN * 64 + ns * 8 + tig * 2;
            atomicAdd(&g_sum[b * C_ + col],     s0);
            atomicAdd(&g_sum[b * C_ + col + 1], s1);
            atomicAdd(&g_sumsq[b * C_ + col],     q0);
            atomicAdd(&g_sumsq[b * C_ + col + 1], q1);
        }
    }
}

// ---------------------------------------------------------------------------
// K3: out = relu((y - mean) * rstd * ls + lb) + X, stats computed inline.
// 2 float4 elements per thread for MLP.
// ---------------------------------------------------------------------------
__global__ __launch_bounds__(256) void k_apply(const float* __restrict__ X,
                                               const float* __restrict__ ls,
                                               const float* __restrict__ lb,
                                               float* __restrict__ out) {
    int base = blockIdx.x * 512 + threadIdx.x;    // two strided float4 slots
    #pragma unroll
    for (int u = 0; u < 2; u++) {
        int idx = base + u * 256;                  // float4 index
        int c4 = idx & 63;
        int m = idx >> 6;
        int bb = m >> 12;
        int cb = c4 * 4;

        float4 y = *(const float4*)&g_y[(size_t)idx * 4];
        float4 x = ((const float4*)X)[idx];
        float4 sm = *(const float4*)&g_sum[bb * C_ + cb];
        float4 sq = *(const float4*)&g_sumsq[bb * C_ + cb];
        float4 s4 = *(const float4*)&ls[cb];
        float4 b4 = *(const float4*)&lb[cb];

        const float inv = 1.f / N_;
        float m0 = sm.x * inv, m1 = sm.y * inv, m2 = sm.z * inv, m3 = sm.w * inv;
        float r0 = rsqrtf(sq.x * inv - m0 * m0 + 1e-6f);
        float r1 = rsqrtf(sq.y * inv - m1 * m1 + 1e-6f);
        float r2 = rsqrtf(sq.z * inv - m2 * m2 + 1e-6f);
        float r3 = rsqrtf(sq.w * inv - m3 * m3 + 1e-6f);

        float4 o;
        o.x = fmaxf((y.x - m0) * r0 * s4.x + b4.x, 0.f) + x.x;
        o.y = fmaxf((y.y - m1) * r1 * s4.y + b4.y, 0.f) + x.y;
        o.z = fmaxf((y.z - m2) * r2 * s4.z + b4.z, 0.f) + x.z;
        o.w = fmaxf((y.w - m3) * r3 * s4.w + b4.w, 0.f) + x.w;
        ((float4*)out)[idx] = o;
    }
}

// ---------------------------------------------------------------------------
extern "C" void kernel_launch(void* const* d_in, const int* in_sizes, int n_in,
                              void* d_out, int out_size) {
    // order: inputs, mask, Wq, bq, Wk, bk, Wv, bv, Wo, bo, ln_scale, ln_bias
    const float* X  = (const float*)d_in[0];
    const float* Wv = (const float*)d_in[6];
    const float* Wo = (const float*)d_in[8];
    const float* ls = (const float*)d_in[10];
    const float* lb = (const float*)d_in[11];
    float* out = (float*)d_out;

    cudaFuncSetAttribute(k_gemm, cudaFuncAttributeMaxDynamicSharedMemorySize,
                         SM_TOTAL);

    k_prep<<<33, 256>>>(Wv, Wo);
    k_gemm<<<M_ / 128, 256, SM_TOTAL>>>(X);
    k_apply<<<M_ * C_ / 4 / 512, 256>>>(X, ls, lb, out);
}

// round 5
// speedup vs baseline: 2.0787x; 1.2362x over previous
#include <cuda_runtime.h>
#include <cuda_bf16.h>
#include <cstdint>

#define B_ 4
#define N_ 4096
#define C_ 256
#define M_ (B_ * N_)

#define ROWB 144      // bytes per SMEM row (64 bf16 = 128B + 16B pad)

// SMEM layout (dynamic) for k_gemm:
#define SM_AHI 0
#define SM_ALO 18432
#define SM_B0  36864            // buffer 0: hi at +0, lo at +36864
#define BUFSZ  73728
#define SM_TOTAL (36864 + 2 * BUFSZ)   // 184320

// ---------------- device scratch ----------------
__device__ float g_Wpart[4][C_ * C_];      // per-kslab partials of Wv@Wo
__device__ __nv_bfloat16 g_Bhi[C_ * C_];   // W^T hi, [n][k]
__device__ __nv_bfloat16 g_Blo[C_ * C_];   // W^T lo, [n][k]
__device__ float g_y[M_ * C_];             // pre-LN activations
__device__ float g_sum[B_ * C_];
__device__ float g_sumsq[B_ * C_];

__device__ __forceinline__ uint32_t smem_u32(const void* p) {
    uint32_t a;
    asm("{ .reg .u64 t; cvta.to.shared.u64 t, %1; cvt.u32.u64 %0, t; }" : "=r"(a) : "l"(p));
    return a;
}
__device__ __forceinline__ void cp16(uint32_t dst, const void* src) {
    asm volatile("cp.async.cg.shared.global [%0], [%1], 16;" :: "r"(dst), "l"(src));
}
__device__ __forceinline__ void cp_commit() {
    asm volatile("cp.async.commit_group;" ::: "memory");
}
template <int N> __device__ __forceinline__ void cp_wait() {
    asm volatile("cp.async.wait_group %0;" :: "n"(N) : "memory");
}
__device__ __forceinline__ void ldmx4(uint32_t* r, uint32_t addr) {
    asm volatile("ldmatrix.sync.aligned.m8n8.x4.shared.b16 {%0,%1,%2,%3}, [%4];"
                 : "=r"(r[0]), "=r"(r[1]), "=r"(r[2]), "=r"(r[3]) : "r"(addr));
}
__device__ __forceinline__ void ldmx2(uint32_t* r, uint32_t addr) {
    asm volatile("ldmatrix.sync.aligned.m8n8.x2.shared.b16 {%0,%1}, [%2];"
                 : "=r"(r[0]), "=r"(r[1]) : "r"(addr));
}
__device__ __forceinline__ void mma16816(float* c, const uint32_t* a, const uint32_t* b) {
    asm volatile(
        "mma.sync.aligned.m16n8k16.row.col.f32.bf16.bf16.f32 "
        "{%0,%1,%2,%3}, {%4,%5,%6,%7}, {%8,%9}, {%0,%1,%2,%3};"
        : "+f"(c[0]), "+f"(c[1]), "+f"(c[2]), "+f"(c[3])
        : "r"(a[0]), "r"(a[1]), "r"(a[2]), "r"(a[3]), "r"(b[0]), "r"(b[1]));
}

// ---------------------------------------------------------------------------
// K1: partial W = Wv@Wo over a 64-wide k-slab. grid (32 rowgroups, 4 kslabs).
// No atomics: each slab writes its own partial buffer.
// ---------------------------------------------------------------------------
__global__ __launch_bounds__(256) void k_prepmm(const float* __restrict__ Wv,
                                                const float* __restrict__ Wo) {
    __shared__ float s_wv[8][64];
    int t = threadIdx.x;
    int i0 = blockIdx.x * 8;
    int k0 = blockIdx.y * 64;

    // load 8 rows x 64 k of Wv
    #pragma unroll
    for (int e = t; e < 512; e += 256)
        s_wv[e >> 6][e & 63] = Wv[(i0 + (e >> 6)) * C_ + k0 + (e & 63)];
    __syncthreads();

    float acc[8] = {};
    #pragma unroll 16
    for (int kk = 0; kk < 64; kk++) {
        float wo = Wo[(k0 + kk) * C_ + t];
        #pragma unroll
        for (int r = 0; r < 8; r++) acc[r] += s_wv[r][kk] * wo;
    }
    float* dst = &g_Wpart[blockIdx.y][i0 * C_ + t];
    #pragma unroll
    for (int r = 0; r < 8; r++) dst[r * C_] = acc[r];
}

// ---------------------------------------------------------------------------
// K2: sum the 4 partials, emit transposed bf16 hi/lo; zero stat accums.
// (Per-channel bias cancels exactly through the N-axis LayerNorm -> dropped.)
// ---------------------------------------------------------------------------
__global__ __launch_bounds__(256) void k_split() {
    int base = blockIdx.x * 1024 + threadIdx.x * 4;
    #pragma unroll
    for (int u = 0; u < 4; u++) {
        int idx = base + u;
        float w = g_Wpart[0][idx] + g_Wpart[1][idx] + g_Wpart[2][idx] + g_Wpart[3][idx];
        int i = idx >> 8;       // k index
        int j = idx & 255;      // n index
        __nv_bfloat16 h = __float2bfloat16(w);
        g_Bhi[j * C_ + i] = h;
        g_Blo[j * C_ + i] = __float2bfloat16(w - __bfloat162float(h));
    }
    if (blockIdx.x < 2) {
        int i = blockIdx.x * 1024 + threadIdx.x * 4;
        if (i < B_ * C_) {
            *(float4*)&g_sum[i] = make_float4(0.f, 0.f, 0.f, 0.f);
            *(float4*)&g_sumsq[i] = make_float4(0.f, 0.f, 0.f, 0.f);
        }
    }
}

// ---------------------------------------------------------------------------
// K3: y = X @ W (split-bf16 HMMA), pipelined; epilogue fuses column stats.
// ---------------------------------------------------------------------------
__global__ __launch_bounds__(256, 1) void k_gemm(const float* __restrict__ X) {
    extern __shared__ char smem[];
    uint32_t sb = smem_u32(smem);
    int t = threadIdx.x, wid = t >> 5, lane = t & 31;
    int warpM = wid >> 2, warpN = wid & 3;
    int m0 = blockIdx.x * 128;
    int q = t & 3, rr = t >> 2;          // loader coords

    float acc[4][8][4];
    #pragma unroll
    for (int i = 0; i < 4; i++)
        #pragma unroll
        for (int j = 0; j < 8; j++)
            #pragma unroll
            for (int r = 0; r < 4; r++) acc[i][j][r] = 0.f;

    uint32_t aBase = sb + SM_AHI +
        (warpM * 64 + ((lane >> 3) & 1) * 8 + (lane & 7)) * ROWB + (lane >> 4) * 16;

    auto issueB = [&](int c, int buf) {
        uint32_t bhi = sb + SM_B0 + buf * BUFSZ;
        uint32_t blo = bhi + 36864;
        const char* shi = (const char*)g_Bhi + c * 128 + q * 32;
        const char* slo = (const char*)g_Blo + c * 128 + q * 32;
        #pragma unroll
        for (int it = 0; it < 4; it++) {
            int row = it * 64 + rr;
            uint32_t d = row * ROWB + q * 32;
            const char* sh = shi + (size_t)row * 512;
            const char* sl = slo + (size_t)row * 512;
            cp16(bhi + d, sh);       cp16(bhi + d + 16, sh + 16);
            cp16(blo + d, sl);       cp16(blo + d + 16, sl + 16);
        }
        cp_commit();
    };
    float areg[32];
    auto loadA = [&](int c) {
        #pragma unroll
        for (int p = 0; p < 2; p++) {
            const float* src = X + (size_t)(m0 + p * 64 + rr) * C_ + c * 64 + q * 16;
            #pragma unroll
            for (int i = 0; i < 4; i++)
                *(float4*)&areg[p * 16 + i * 4] = *(const float4*)(src + i * 4);
        }
    };
    auto storeA = [&]() {
        #pragma unroll
        for (int p = 0; p < 2; p++) {
            int row = p * 64 + rr;
            __nv_bfloat16 h[16], l[16];
            #pragma unroll
            for (int i = 0; i < 16; i++) {
                float v = areg[p * 16 + i];
                h[i] = __float2bfloat16(v);
                l[i] = __float2bfloat16(v - __bfloat162float(h[i]));
            }
            char* dh = smem + SM_AHI + row * ROWB + q * 32;
            char* dl = smem + SM_ALO + row * ROWB + q * 32;
            *(uint4*)dh = *(uint4*)&h[0]; *(uint4*)(dh + 16) = *(uint4*)&h[8];
            *(uint4*)dl = *(uint4*)&l[0]; *(uint4*)(dl + 16) = *(uint4*)&l[8];
        }
    };

    issueB(0, 0);
    loadA(0);

    for (int c = 0; c < 4; c++) {
        if (c < 3) issueB(c + 1, (c + 1) & 1);
        storeA();
        if (c < 3) cp_wait<1>(); else cp_wait<0>();
        __syncthreads();
        if (c < 3) loadA(c + 1);           // DRAM latency hides under MMAs

        uint32_t bBase = sb + SM_B0 + (c & 1) * BUFSZ +
            (warpN * 64 + (lane & 7)) * ROWB + ((lane >> 3) & 1) * 16;
        #pragma unroll
        for (int ks = 0; ks < 4; ks++) {
            uint32_t ah[4][4], al[4][4];
            #pragma unroll
            for (int ms = 0; ms < 4; ms++) {
                uint32_t addr = aBase + ms * (16 * ROWB) + ks * 32;
                ldmx4(ah[ms], addr);
                ldmx4(al[ms], addr + (SM_ALO - SM_AHI));
            }
            #pragma unroll
            for (int ns = 0; ns < 8; ns++) {
                uint32_t bh[2], bl[2];
                uint32_t addr = bBase + ns * (8 * ROWB) + ks * 32;
                ldmx2(bh, addr);
                ldmx2(bl, addr + 36864);
                #pragma unroll
                for (int ms = 0; ms < 4; ms++) {
                    mma16816(acc[ms][ns], ah[ms], bh);
                    mma16816(acc[ms][ns], ah[ms], bl);
                    mma16816(acc[ms][ns], al[ms], bh);
                }
            }
        }
        __syncthreads();
    }

    // ---- epilogue: write y ----
    int gid = lane >> 2, tig = lane & 3;
    #pragma unroll
    for (int ms = 0; ms < 4; ms++) {
        int row0 = m0 + warpM * 64 + ms * 16 + gid;
        #pragma unroll
        for (int half = 0; half < 2; half++) {
            float* dst = g_y + (size_t)(row0 + half * 8) * C_ + warpN * 64 + tig * 2;
            #pragma unroll
            for (int ns = 0; ns < 8; ns++) {
                float2 v;
                v.x = acc[ms][ns][half * 2 + 0];
                v.y = acc[ms][ns][half * 2 + 1];
                *(float2*)(dst + ns * 8) = v;
            }
        }
    }

    // ---- fused column stats ----
    int b = m0 >> 12;
    #pragma unroll
    for (int ns = 0; ns < 8; ns++) {
        float s0 = 0.f, s1 = 0.f, q0 = 0.f, q1 = 0.f;
        #pragma unroll
        for (int ms = 0; ms < 4; ms++)
            #pragma unroll
            for (int half = 0; half < 2; half++) {
                float v0 = acc[ms][ns][half * 2 + 0];
                float v1 = acc[ms][ns][half * 2 + 1];
                s0 += v0; q0 += v0 * v0;
                s1 += v1; q1 += v1 * v1;
            }
        #pragma unroll
        for (int off = 4; off < 32; off <<= 1) {
            s0 += __shfl_xor_sync(0xFFFFFFFFu, s0, off);
            s1 += __shfl_xor_sync(0xFFFFFFFFu, s1, off);
            q0 += __shfl_xor_sync(0xFFFFFFFFu, q0, off);
            q1 += __shfl_xor_sync(0xFFFFFFFFu, q1, off);
        }
        if (gid == 0) {
            int col = warpN * 64 + ns * 8 + tig * 2;
            atomicAdd(&g_sum[b * C_ + col],     s0);
            atomicAdd(&g_sum[b * C_ + col + 1], s1);
            atomicAdd(&g_sumsq[b * C_ + col],     q0);
            atomicAdd(&g_sumsq[b * C_ + col + 1], q1);
        }
    }
}

// ---------------------------------------------------------------------------
// K4: out = relu((y - mean) * rstd * ls + lb) + X, stats computed inline.
// ---------------------------------------------------------------------------
__global__ __launch_bounds__(256) void k_apply(const float* __restrict__ X,
                                               const float* __restrict__ ls,
                                               const float* __restrict__ lb,
                                               float* __restrict__ out) {
    int base = blockIdx.x * 512 + threadIdx.x;    // two strided float4 slots
    #pragma unroll
    for (int u = 0; u < 2; u++) {
        int idx = base + u * 256;                  // float4 index
        int c4 = idx & 63;
        int m = idx >> 6;
        int bb = m >> 12;
        int cb = c4 * 4;

        float4 y = *(const float4*)&g_y[(size_t)idx * 4];
        float4 x = ((const float4*)X)[idx];
        float4 sm = *(const float4*)&g_sum[bb * C_ + cb];
        float4 sq = *(const float4*)&g_sumsq[bb * C_ + cb];
        float4 s4 = *(const float4*)&ls[cb];
        float4 b4 = *(const float4*)&lb[cb];

        const float inv = 1.f / N_;
        float m0 = sm.x * inv, m1 = sm.y * inv, m2 = sm.z * inv, m3 = sm.w * inv;
        float r0 = rsqrtf(sq.x * inv - m0 * m0 + 1e-6f);
        float r1 = rsqrtf(sq.y * inv - m1 * m1 + 1e-6f);
        float r2 = rsqrtf(sq.z * inv - m2 * m2 + 1e-6f);
        float r3 = rsqrtf(sq.w * inv - m3 * m3 + 1e-6f);

        float4 o;
        o.x = fmaxf((y.x - m0) * r0 * s4.x + b4.x, 0.f) + x.x;
        o.y = fmaxf((y.y - m1) * r1 * s4.y + b4.y, 0.f) + x.y;
        o.z = fmaxf((y.z - m2) * r2 * s4.z + b4.z, 0.f) + x.z;
        o.w = fmaxf((y.w - m3) * r3 * s4.w + b4.w, 0.f) + x.w;
        ((float4*)out)[idx] = o;
    }
}

// ---------------------------------------------------------------------------
extern "C" void kernel_launch(void* const* d_in, const int* in_sizes, int n_in,
                              void* d_out, int out_size) {
    // order: inputs, mask, Wq, bq, Wk, bk, Wv, bv, Wo, bo, ln_scale, ln_bias
    const float* X  = (const float*)d_in[0];
    const float* Wv = (const float*)d_in[6];
    const float* Wo = (const float*)d_in[8];
    const float* ls = (const float*)d_in[10];
    const float* lb = (const float*)d_in[11];
    float* out = (float*)d_out;

    cudaFuncSetAttribute(k_gemm, cudaFuncAttributeMaxDynamicSharedMemorySize,
                         SM_TOTAL);

    k_prepmm<<<dim3(32, 4), 256>>>(Wv, Wo);
    k_split<<<64, 256>>>();
    k_gemm<<<M_ / 128, 256, SM_TOTAL>>>(X);
    k_apply<<<M_ * C_ / 4 / 512, 256>>>(X, ls, lb, out);
}